// round 5
// baseline (speedup 1.0000x reference)
#include <cuda_runtime.h>
#include <cstdint>

// Router_63900523430579 (GB300/sm_103): scores = x[32768,2048] @ W[64,2048]^T
// via mma.sync.m16n8k8 tf32 (baseline PTX, works at compute_103).
// out f32: [0,65536) top2 idx ; [65536,131072) top2 weights ; [131072] aux loss

#define KDIM   2048
#define NTOK   32768
#define NEXP   64
#define MTILE  128
#define NCTA   (NTOK / MTILE)          // 256
#define CK     32                      // K floats per chunk
#define NCHUNK (KDIM / CK)             // 64
#define RW     36                      // padded smem row stride (floats)
#define STAGEF ((MTILE + NEXP) * RW)   // 6912 floats per stage
#define SMEM_REQ (2 * STAGEF * 4)      // 55296 B
#define DELTA1 2.5e-3f
#define DELTA2 1.0e-4f

__device__ float g_part[NCTA * NEXP];
__device__ int   g_cnt, g_cnt2;
__device__ int   g_list[NTOK], g_list2[NTOK];

__device__ __forceinline__ float to_tf32(float v) {
    float r;
    asm("cvt.rna.tf32.f32 %0, %1;" : "=f"(r) : "f"(v));
    return r;
}
__device__ __forceinline__ void mma8(float* d, uint32_t a0, uint32_t a1,
                                     uint32_t a2, uint32_t a3,
                                     uint32_t b0, uint32_t b1) {
    asm volatile("mma.sync.aligned.m16n8k8.row.col.f32.tf32.tf32.f32 "
                 "{%0,%1,%2,%3},{%4,%5,%6,%7},{%8,%9},{%0,%1,%2,%3};"
                 : "+f"(d[0]), "+f"(d[1]), "+f"(d[2]), "+f"(d[3])
                 : "r"(a0), "r"(a1), "r"(a2), "r"(a3), "r"(b0), "r"(b1));
}

__global__ void reset_kernel() { g_cnt = 0; g_cnt2 = 0; }

// ---------------- main router ----------------
__global__ void __launch_bounds__(256, 2)
router_kernel(const float* __restrict__ x, const float* __restrict__ W,
              float* __restrict__ out) {
    extern __shared__ float sm[];
    const int tid = threadIdx.x;
    const int wid = tid >> 5, lane = tid & 31;
    const int lq = lane & 3, lr = lane >> 2;          // fragment coords

    const float* xg = x + (size_t)blockIdx.x * MTILE * KDIM;

    float4 rx[4], rw[2];
    auto ldg_chunk = [&](int c) {
        #pragma unroll
        for (int v = 0; v < 4; v++) {
            int fi = tid + 256 * v;                   // x: 128 rows x 8 float4
            int r = fi >> 3, c4 = fi & 7;
            rx[v] = *(const float4*)(xg + (size_t)r * KDIM + c * CK + c4 * 4);
        }
        #pragma unroll
        for (int v = 0; v < 2; v++) {
            int fi = tid + 256 * v;                   // W: 64 rows x 8 float4
            int e = fi >> 3, c4 = fi & 7;
            rw[v] = *(const float4*)(W + (size_t)e * KDIM + c * CK + c4 * 4);
        }
    };
    auto sts_chunk = [&](int c) {
        float* st = sm + (c & 1) * STAGEF;
        #pragma unroll
        for (int v = 0; v < 4; v++) {
            int fi = tid + 256 * v;
            int r = fi >> 3, c4 = fi & 7;
            float4 t = rx[v];
            t.x = to_tf32(t.x); t.y = to_tf32(t.y);
            t.z = to_tf32(t.z); t.w = to_tf32(t.w);
            *(float4*)(st + r * RW + c4 * 4) = t;
        }
        #pragma unroll
        for (int v = 0; v < 2; v++) {
            int fi = tid + 256 * v;
            int e = fi >> 3, c4 = fi & 7;
            float4 t = rw[v];
            t.x = to_tf32(t.x); t.y = to_tf32(t.y);
            t.z = to_tf32(t.z); t.w = to_tf32(t.w);
            *(float4*)(st + MTILE * RW + e * RW + c4 * 4) = t;
        }
    };

    float acc[8][4];
    #pragma unroll
    for (int j = 0; j < 8; j++)
        #pragma unroll
        for (int v = 0; v < 4; v++) acc[j][v] = 0.0f;

    ldg_chunk(0); sts_chunk(0); ldg_chunk(1);
    __syncthreads();

    for (int c = 0; c < NCHUNK; c++) {
        const float* xb = sm + (c & 1) * STAGEF;
        const float* wb = xb + MTILE * RW;
        const float* xrow = xb + (wid * 16 + lr) * RW + lq;
        const float* wrow = wb + lr * RW + lq;
        #pragma unroll
        for (int s = 0; s < 4; s++) {
            uint32_t a0 = __float_as_uint(xrow[s * 8]);
            uint32_t a1 = __float_as_uint(xrow[8 * RW + s * 8]);
            uint32_t a2 = __float_as_uint(xrow[s * 8 + 4]);
            uint32_t a3 = __float_as_uint(xrow[8 * RW + s * 8 + 4]);
            #pragma unroll
            for (int j = 0; j < 8; j++) {
                uint32_t b0 = __float_as_uint(wrow[j * 8 * RW + s * 8]);
                uint32_t b1 = __float_as_uint(wrow[j * 8 * RW + s * 8 + 4]);
                mma8(acc[j], a0, a1, a2, a3, b0, b1);
            }
        }
        if (c + 1 < NCHUNK) sts_chunk(c + 1);
        __syncthreads();
        if (c + 2 < NCHUNK) ldg_chunk(c + 2);
    }

    // ---- score overlay: sc[128][65], mm[128], iz[128] ----
    float* sc = sm;
    float* mm = sc + 128 * 65;
    float* iz = mm + 128;

    #pragma unroll
    for (int j = 0; j < 8; j++) {
        int r0 = wid * 16 + lr;
        sc[r0 * 65 + j * 8 + lq * 2]           = acc[j][0];
        sc[r0 * 65 + j * 8 + lq * 2 + 1]       = acc[j][1];
        sc[(r0 + 8) * 65 + j * 8 + lq * 2]     = acc[j][2];
        sc[(r0 + 8) * 65 + j * 8 + lq * 2 + 1] = acc[j][3];
    }
    __syncthreads();

    if (tid < 128) {
        const int t = tid;
        const float* row = sc + t * 65;
        float m1 = -3e38f, m2 = -3e38f, m3 = -3e38f; int i1 = 0, i2 = 0;
        #pragma unroll 8
        for (int e = 0; e < 64; e++) {
            float v = row[e];
            if (v > m1)      { m3 = m2; m2 = m1; i2 = i1; m1 = v; i1 = e; }
            else if (v > m2) { m3 = m2; m2 = v; i2 = e; }
            else if (v > m3) { m3 = v; }
        }
        float Z = 0.0f;
        #pragma unroll 8
        for (int e = 0; e < 64; e++) Z += __expf(row[e] - m1);
        mm[t] = m1;
        iz[t] = 1.0f / Z;

        float e2 = __expf(m2 - m1);
        float w1 = 1.0f / (1.0f + e2);
        size_t T = (size_t)blockIdx.x * MTILE + t;
        out[2 * T]     = (float)i1;
        out[2 * T + 1] = (float)i2;
        out[2 * (size_t)NTOK + 2 * T]     = w1;
        out[2 * (size_t)NTOK + 2 * T + 1] = e2 * w1;
        if ((m1 - m2) < DELTA1 || (m2 - m3) < DELTA1) {
            int w = atomicAdd(&g_cnt, 1);
            g_list[w] = (int)T;
        }
    }
    __syncthreads();

    if (tid < NEXP) {
        float s = 0.0f;
        for (int t = 0; t < MTILE; t++)
            s += __expf(sc[t * 65 + tid] - mm[t]) * iz[t];
        g_part[blockIdx.x * NEXP + tid] = s;
    }
}

// ---- stage-1 fixup: exact fp32, W staged through smem ----
__global__ void __launch_bounds__(256)
fixup32_kernel(const float* __restrict__ x, const float* __restrict__ W,
               float* __restrict__ out) {
    __shared__ float wsm[64 * RW];
    __shared__ float xsm[4 * RW];
    __shared__ float scm[4 * 65];
    __shared__ int   toks[4];
    const int n = g_cnt;
    const int tid = threadIdx.x;
    const int slot = tid >> 6, e = tid & 63;

    for (int base = blockIdx.x * 4; base < n; base += gridDim.x * 4) {
        if (tid < 4) toks[tid] = (base + tid < n) ? g_list[base + tid] : g_list[base];
        __syncthreads();
        float acc = 0.0f;
        for (int kc = 0; kc < 64; kc++) {
            #pragma unroll
            for (int v = 0; v < 2; v++) {
                int fi = tid + 256 * v;
                int r = fi >> 3, c4 = fi & 7;
                *(float4*)&wsm[r * RW + c4 * 4] =
                    *(const float4*)&W[(size_t)r * KDIM + kc * 32 + c4 * 4];
            }
            if (tid < 32) {
                int tok = tid >> 3, c4 = tid & 7;
                *(float4*)&xsm[tok * RW + c4 * 4] =
                    *(const float4*)&x[(size_t)toks[tok] * KDIM + kc * 32 + c4 * 4];
            }
            __syncthreads();
            #pragma unroll 8
            for (int k = 0; k < 32; k++)
                acc += wsm[e * RW + k] * xsm[slot * RW + k];
            __syncthreads();
        }
        scm[slot * 65 + e] = acc;
        __syncthreads();
        if (tid < 4 && base + tid < n) {
            const int tok = toks[tid];
            const float* row = scm + tid * 65;
            float m1 = -3e38f, m2 = -3e38f, m3 = -3e38f; int i1 = 0, i2 = 0;
            for (int q = 0; q < 64; q++) {
                float v = row[q];
                if (v > m1)      { m3 = m2; m2 = m1; i2 = i1; m1 = v; i1 = q; }
                else if (v > m2) { m3 = m2; m2 = v; i2 = q; }
                else if (v > m3) { m3 = v; }
            }
            if ((m1 - m2) < DELTA2 || (m2 - m3) < DELTA2) {
                int q = atomicAdd(&g_cnt2, 1);
                g_list2[q] = tok;
            } else {
                float e2 = expf(m2 - m1);
                float w1 = 1.0f / (1.0f + e2);
                out[2 * (size_t)tok]     = (float)i1;
                out[2 * (size_t)tok + 1] = (float)i2;
                out[2 * (size_t)NTOK + 2 * (size_t)tok]     = w1;
                out[2 * (size_t)NTOK + 2 * (size_t)tok + 1] = e2 * w1;
            }
        }
        __syncthreads();
    }
}

// ---- stage-2 fixup: exact fp64 ----
__global__ void __launch_bounds__(128)
fixup64_kernel(const float* __restrict__ x, const float* __restrict__ W,
               float* __restrict__ out) {
    __shared__ double sh[64];
    const int n = g_cnt2;
    const int wi = threadIdx.x >> 5, l = threadIdx.x & 31;
    for (int w = blockIdx.x; w < n; w += gridDim.x) {
        const int tok = g_list2[w];
        const float* xr = x + (size_t)tok * KDIM;
        for (int em = 0; em < 16; em++) {
            int e = wi + em * 4;
            const float* wr = W + (size_t)e * KDIM;
            double s = 0.0;
            for (int j = 0; j < 64; j++)
                s += (double)xr[j * 32 + l] * (double)wr[j * 32 + l];
            #pragma unroll
            for (int o = 16; o > 0; o >>= 1) s += __shfl_xor_sync(0xffffffffu, s, o);
            if (l == 0) sh[e] = s;
        }
        __syncthreads();
        if (threadIdx.x == 0) {
            double m1 = -1e300, m2 = -1e300; int i1 = 0, i2 = 0;
            for (int q = 0; q < 64; q++)
                if (sh[q] > m1) { m1 = sh[q]; i1 = q; }
            for (int q = 0; q < 64; q++) {
                if (q == i1) continue;
                if (sh[q] > m2) { m2 = sh[q]; i2 = q; }
            }
            double e2 = exp(m2 - m1);
            double w1 = 1.0 / (1.0 + e2);
            out[2 * (size_t)tok]     = (float)i1;
            out[2 * (size_t)tok + 1] = (float)i2;
            out[2 * (size_t)NTOK + 2 * (size_t)tok]     = (float)w1;
            out[2 * (size_t)NTOK + 2 * (size_t)tok + 1] = (float)(e2 * w1);
        }
        __syncthreads();
    }
}

// ---- aux loss ----
__global__ void __launch_bounds__(256)
aux_kernel(float* __restrict__ out) {
    __shared__ float ps[4][64];
    const int tid = threadIdx.x;
    const int e = tid & 63, part = tid >> 6;
    float s = 0.0f;
    for (int c = part * 64; c < part * 64 + 64; c++)
        s += g_part[c * NEXP + e];
    ps[part][e] = s;
    __syncthreads();
    if (tid < 64) {
        float u = (ps[0][tid] + ps[1][tid] + ps[2][tid] + ps[3][tid]) * (1.0f / (float)NTOK);
        ps[0][tid] = u * u;
    }
    __syncthreads();
    if (tid < 32) {
        float v = ps[0][tid] + ps[0][tid + 32];
        #pragma unroll
        for (int o = 16; o > 0; o >>= 1) v += __shfl_xor_sync(0xffffffffu, v, o);
        if (tid == 0) out[131072] = 64.0f * v;
    }
}

extern "C" void kernel_launch(void* const* d_in, const int* in_sizes, int n_in,
                              void* d_out, int out_size) {
    const float* x = (const float*)d_in[0];
    const float* W = (const float*)d_in[1];
    float* out = (float*)d_out;
    cudaFuncSetAttribute(router_kernel, cudaFuncAttributeMaxDynamicSharedMemorySize, SMEM_REQ);
    reset_kernel<<<1, 1>>>();
    router_kernel<<<NCTA, 256, SMEM_REQ>>>(x, W, out);
    fixup32_kernel<<<128, 256>>>(x, W, out);
    fixup64_kernel<<<32, 128>>>(x, W, out);
    aux_kernel<<<1, 256>>>(out);
}

// round 6
// speedup vs baseline: 1.1317x; 1.1317x over previous
#include <cuda_runtime.h>
#include <cstdint>

// Router_63900523430579 (GB300/sm_103): scores = x[32768,2048] @ W[64,2048]^T
// via mma.sync.m16n8k8 tf32 (baseline PTX). Raw f32 operands (HW truncates to
// tf32); exactness restored by screen->fp32->fp64 fixup chain.
// out f32: [0,65536) top2 idx ; [65536,131072) top2 weights ; [131072] aux loss

#define KDIM   2048
#define NTOK   32768
#define NEXP   64
#define MTILE  128
#define NCTA   (NTOK / MTILE)          // 256
#define CK     32                      // K floats per chunk
#define NCHUNK (KDIM / CK)             // 64
#define RW     40                      // padded smem row stride (floats)
#define STAGEF ((MTILE + NEXP) * RW)   // 7680 floats per stage
#define SMEM_REQ (2 * STAGEF * 4)      // 61440 B
#define DELTA1 3.0e-3f
#define DELTA2 1.0e-4f

__device__ float g_part[NCTA * NEXP];
__device__ int   g_cnt, g_cnt2;
__device__ int   g_list[NTOK], g_list2[NTOK];

__device__ __forceinline__ void mma8(float* d, uint32_t a0, uint32_t a1,
                                     uint32_t a2, uint32_t a3,
                                     uint32_t b0, uint32_t b1) {
    asm volatile("mma.sync.aligned.m16n8k8.row.col.f32.tf32.tf32.f32 "
                 "{%0,%1,%2,%3},{%4,%5,%6,%7},{%8,%9},{%0,%1,%2,%3};"
                 : "+f"(d[0]), "+f"(d[1]), "+f"(d[2]), "+f"(d[3])
                 : "r"(a0), "r"(a1), "r"(a2), "r"(a3), "r"(b0), "r"(b1));
}

__global__ void reset_kernel() { g_cnt = 0; g_cnt2 = 0; }

// ---------------- main router ----------------
__global__ void __launch_bounds__(256, 2)
router_kernel(const float* __restrict__ x, const float* __restrict__ W,
              float* __restrict__ out) {
    extern __shared__ float sm[];
    const int tid = threadIdx.x;
    const int wid = tid >> 5, lane = tid & 31;
    const int lq = lane & 3, lr = lane >> 2;          // fragment coords

    const float* xg = x + (size_t)blockIdx.x * MTILE * KDIM;

    float4 rx[4], rw[2];
    auto ldg_chunk = [&](int c) {
        #pragma unroll
        for (int v = 0; v < 4; v++) {
            int fi = tid + 256 * v;                   // x: 128 rows x 8 float4
            int r = fi >> 3, c4 = fi & 7;
            rx[v] = *(const float4*)(xg + (size_t)r * KDIM + c * CK + c4 * 4);
        }
        #pragma unroll
        for (int v = 0; v < 2; v++) {
            int fi = tid + 256 * v;                   // W: 64 rows x 8 float4
            int e = fi >> 3, c4 = fi & 7;
            rw[v] = *(const float4*)(W + (size_t)e * KDIM + c * CK + c4 * 4);
        }
    };
    auto sts_chunk = [&](int c) {
        float* st = sm + (c & 1) * STAGEF;
        // x: linear float4 rows
        #pragma unroll
        for (int v = 0; v < 4; v++) {
            int fi = tid + 256 * v;
            int r = fi >> 3, c4 = fi & 7;
            *(float4*)(st + r * RW + c4 * 4) = rx[v];
        }
        // W: k-interleaved within each 8-group: col = (c4>>1)*8 + 2t + (c4&1)
        #pragma unroll
        for (int v = 0; v < 2; v++) {
            int fi = tid + 256 * v;
            int e = fi >> 3, c4 = fi & 7;
            float* wr = st + MTILE * RW + e * RW + (c4 >> 1) * 8 + (c4 & 1);
            wr[0] = rw[v].x; wr[2] = rw[v].y; wr[4] = rw[v].z; wr[6] = rw[v].w;
        }
    };

    float acc[8][4];
    #pragma unroll
    for (int j = 0; j < 8; j++)
        #pragma unroll
        for (int v = 0; v < 4; v++) acc[j][v] = 0.0f;

    ldg_chunk(0); sts_chunk(0); ldg_chunk(1);
    __syncthreads();

    for (int c = 0; c < NCHUNK; c++) {
        const float* xb = sm + (c & 1) * STAGEF;
        const float* wb = xb + MTILE * RW;
        const float* xrow = xb + (wid * 16 + lr) * RW + lq;
        const float* wrow = wb + lr * RW + 2 * lq;
        #pragma unroll
        for (int s = 0; s < 4; s++) {
            uint32_t a0 = __float_as_uint(xrow[s * 8]);
            uint32_t a1 = __float_as_uint(xrow[8 * RW + s * 8]);
            uint32_t a2 = __float_as_uint(xrow[s * 8 + 4]);
            uint32_t a3 = __float_as_uint(xrow[8 * RW + s * 8 + 4]);
            #pragma unroll
            for (int j = 0; j < 8; j++) {
                float2 b = *(const float2*)(wrow + j * 8 * RW + s * 8);
                mma8(acc[j], a0, a1, a2, a3,
                     __float_as_uint(b.x), __float_as_uint(b.y));
            }
        }
        if (c + 1 < NCHUNK) sts_chunk(c + 1);
        __syncthreads();
        if (c + 2 < NCHUNK) ldg_chunk(c + 2);
    }

    // ---- score overlay: sc[128][65], mm[128], iz[128] ----
    float* sc = sm;
    float* mm = sc + 128 * 65;
    float* iz = mm + 128;

    #pragma unroll
    for (int j = 0; j < 8; j++) {
        int r0 = wid * 16 + lr;
        sc[r0 * 65 + j * 8 + lq * 2]           = acc[j][0];
        sc[r0 * 65 + j * 8 + lq * 2 + 1]       = acc[j][1];
        sc[(r0 + 8) * 65 + j * 8 + lq * 2]     = acc[j][2];
        sc[(r0 + 8) * 65 + j * 8 + lq * 2 + 1] = acc[j][3];
    }
    __syncthreads();

    if (tid < 128) {
        const int t = tid;
        const float* row = sc + t * 65;
        float m1 = -3e38f, m2 = -3e38f, m3 = -3e38f; int i1 = 0, i2 = 0;
        #pragma unroll 8
        for (int e = 0; e < 64; e++) {
            float v = row[e];
            if (v > m1)      { m3 = m2; m2 = m1; i2 = i1; m1 = v; i1 = e; }
            else if (v > m2) { m3 = m2; m2 = v; i2 = e; }
            else if (v > m3) { m3 = v; }
        }
        float Z = 0.0f;
        #pragma unroll 8
        for (int e = 0; e < 64; e++) Z += __expf(row[e] - m1);
        mm[t] = m1;
        iz[t] = 1.0f / Z;

        float e2 = __expf(m2 - m1);
        float w1 = 1.0f / (1.0f + e2);
        size_t T = (size_t)blockIdx.x * MTILE + t;
        out[2 * T]     = (float)i1;
        out[2 * T + 1] = (float)i2;
        out[2 * (size_t)NTOK + 2 * T]     = w1;
        out[2 * (size_t)NTOK + 2 * T + 1] = e2 * w1;
        if ((m1 - m2) < DELTA1 || (m2 - m3) < DELTA1) {
            int w = atomicAdd(&g_cnt, 1);
            g_list[w] = (int)T;
        }
    }
    __syncthreads();

    if (tid < NEXP) {
        float s = 0.0f;
        for (int t = 0; t < MTILE; t++)
            s += __expf(sc[t * 65 + tid] - mm[t]) * iz[t];
        g_part[blockIdx.x * NEXP + tid] = s;
    }
}

// ---- stage-1 fixup: exact fp32, W staged through smem ----
__global__ void __launch_bounds__(256)
fixup32_kernel(const float* __restrict__ x, const float* __restrict__ W,
               float* __restrict__ out) {
    __shared__ float wsm[64 * 36];
    __shared__ float xsm[4 * 36];
    __shared__ float scm[4 * 65];
    __shared__ int   toks[4];
    const int n = g_cnt;
    const int tid = threadIdx.x;
    const int slot = tid >> 6, e = tid & 63;

    for (int base = blockIdx.x * 4; base < n; base += gridDim.x * 4) {
        if (tid < 4) toks[tid] = (base + tid < n) ? g_list[base + tid] : g_list[base];
        __syncthreads();
        float acc = 0.0f;
        for (int kc = 0; kc < 64; kc++) {
            #pragma unroll
            for (int v = 0; v < 2; v++) {
                int fi = tid + 256 * v;
                int r = fi >> 3, c4 = fi & 7;
                *(float4*)&wsm[r * 36 + c4 * 4] =
                    *(const float4*)&W[(size_t)r * KDIM + kc * 32 + c4 * 4];
            }
            if (tid < 32) {
                int tok = tid >> 3, c4 = tid & 7;
                *(float4*)&xsm[tok * 36 + c4 * 4] =
                    *(const float4*)&x[(size_t)toks[tok] * KDIM + kc * 32 + c4 * 4];
            }
            __syncthreads();
            #pragma unroll 8
            for (int k = 0; k < 32; k++)
                acc += wsm[e * 36 + k] * xsm[slot * 36 + k];
            __syncthreads();
        }
        scm[slot * 65 + e] = acc;
        __syncthreads();
        if (tid < 4 && base + tid < n) {
            const int tok = toks[tid];
            const float* row = scm + tid * 65;
            float m1 = -3e38f, m2 = -3e38f, m3 = -3e38f; int i1 = 0, i2 = 0;
            for (int q = 0; q < 64; q++) {
                float v = row[q];
                if (v > m1)      { m3 = m2; m2 = m1; i2 = i1; m1 = v; i1 = q; }
                else if (v > m2) { m3 = m2; m2 = v; i2 = q; }
                else if (v > m3) { m3 = v; }
            }
            if ((m1 - m2) < DELTA2 || (m2 - m3) < DELTA2) {
                int q = atomicAdd(&g_cnt2, 1);
                g_list2[q] = tok;
            } else {
                float e2 = expf(m2 - m1);
                float w1 = 1.0f / (1.0f + e2);
                out[2 * (size_t)tok]     = (float)i1;
                out[2 * (size_t)tok + 1] = (float)i2;
                out[2 * (size_t)NTOK + 2 * (size_t)tok]     = w1;
                out[2 * (size_t)NTOK + 2 * (size_t)tok + 1] = e2 * w1;
            }
        }
        __syncthreads();
    }
}

// ---- stage-2 fixup (blocks 0..127): exact fp64, 1 token/block, ILP-4
// ---- aux loss      (block 128): expert-usage reduction
__global__ void __launch_bounds__(256)
fixup64_aux_kernel(const float* __restrict__ x, const float* __restrict__ W,
                   float* __restrict__ out) {
    if (blockIdx.x == 128) {   // ---- aux path ----
        __shared__ float ps[4][64];
        const int tid = threadIdx.x;
        const int e = tid & 63, part = tid >> 6;
        float s = 0.0f;
        for (int c = part * 64; c < part * 64 + 64; c++)
            s += g_part[c * NEXP + e];
        ps[part][e] = s;
        __syncthreads();
        if (tid < 64) {
            float u = (ps[0][tid] + ps[1][tid] + ps[2][tid] + ps[3][tid]) * (1.0f / (float)NTOK);
            ps[0][tid] = u * u;
        }
        __syncthreads();
        if (tid < 32) {
            float v = ps[0][tid] + ps[0][tid + 32];
            #pragma unroll
            for (int o = 16; o > 0; o >>= 1) v += __shfl_xor_sync(0xffffffffu, v, o);
            if (tid == 0) out[131072] = 64.0f * v;
        }
        return;
    }
    // ---- fp64 fixup path ----
    __shared__ double sh[64];
    const int n = g_cnt2;
    const int wi = threadIdx.x >> 5, l = threadIdx.x & 31;
    for (int w = blockIdx.x; w < n; w += 128) {
        const int tok = g_list2[w];
        const float* xr = x + (size_t)tok * KDIM;
        #pragma unroll 1
        for (int e8 = 0; e8 < 8; e8++) {
            int e = wi * 8 + e8;
            const float* wr = W + (size_t)e * KDIM;
            double c0 = 0.0, c1 = 0.0, c2 = 0.0, c3 = 0.0;
            #pragma unroll 4
            for (int j = 0; j < 64; j += 4) {
                c0 += (double)xr[(j + 0) * 32 + l] * (double)wr[(j + 0) * 32 + l];
                c1 += (double)xr[(j + 1) * 32 + l] * (double)wr[(j + 1) * 32 + l];
                c2 += (double)xr[(j + 2) * 32 + l] * (double)wr[(j + 2) * 32 + l];
                c3 += (double)xr[(j + 3) * 32 + l] * (double)wr[(j + 3) * 32 + l];
            }
            double s = (c0 + c1) + (c2 + c3);
            #pragma unroll
            for (int o = 16; o > 0; o >>= 1) s += __shfl_xor_sync(0xffffffffu, s, o);
            if (l == 0) sh[e] = s;
        }
        __syncthreads();
        if (threadIdx.x == 0) {
            double m1 = -1e300, m2 = -1e300; int i1 = 0, i2 = 0;
            for (int q = 0; q < 64; q++)
                if (sh[q] > m1) { m1 = sh[q]; i1 = q; }
            for (int q = 0; q < 64; q++) {
                if (q == i1) continue;
                if (sh[q] > m2) { m2 = sh[q]; i2 = q; }
            }
            double e2 = exp(m2 - m1);
            double w1 = 1.0 / (1.0 + e2);
            out[2 * (size_t)tok]     = (float)i1;
            out[2 * (size_t)tok + 1] = (float)i2;
            out[2 * (size_t)NTOK + 2 * (size_t)tok]     = (float)w1;
            out[2 * (size_t)NTOK + 2 * (size_t)tok + 1] = (float)(e2 * w1);
        }
        __syncthreads();
    }
}

extern "C" void kernel_launch(void* const* d_in, const int* in_sizes, int n_in,
                              void* d_out, int out_size) {
    const float* x = (const float*)d_in[0];
    const float* W = (const float*)d_in[1];
    float* out = (float*)d_out;
    cudaFuncSetAttribute(router_kernel, cudaFuncAttributeMaxDynamicSharedMemorySize, SMEM_REQ);
    reset_kernel<<<1, 1>>>();
    router_kernel<<<NCTA, 256, SMEM_REQ>>>(x, W, out);
    fixup32_kernel<<<128, 256>>>(x, W, out);
    fixup64_aux_kernel<<<129, 256>>>(x, W, out);
}

// round 7
// speedup vs baseline: 1.5619x; 1.3802x over previous
#include <cuda_runtime.h>
#include <cstdint>

// Router_63900523430579 (GB300/sm_103): scores = x[32768,2048] @ W[64,2048]^T
// via mma.sync.m16n8k8 tf32. Exact indices restored by screen->fp32->fp64 chain.
// out f32: [0,65536) top2 idx ; [65536,131072) top2 weights ; [131072] aux loss

#define KDIM   2048
#define NTOK   32768
#define NEXP   64
#define MTILE  256
#define NCTA   (NTOK / MTILE)          // 128
#define CK     32                      // K floats per chunk
#define NCHUNK (KDIM / CK)             // 64
#define RW     40                      // smem row stride (floats)
#define STAGEF ((MTILE + NEXP) * RW)   // 12800 floats / stage
#define SMEM_REQ (2 * STAGEF * 4)      // 102400 B
#define DELTA1 3.0e-3f
#define DELTA2 1.0e-4f

__device__ float    g_part[NCTA * NEXP];
__device__ int      g_cnt, g_cnt2;
__device__ int      g_list[NTOK], g_list2[NTOK];
__device__ unsigned g_cand[NTOK];

__device__ __forceinline__ void mma8(float* d, uint32_t a0, uint32_t a1,
                                     uint32_t a2, uint32_t a3,
                                     uint32_t b0, uint32_t b1) {
    asm volatile("mma.sync.aligned.m16n8k8.row.col.f32.tf32.tf32.f32 "
                 "{%0,%1,%2,%3},{%4,%5,%6,%7},{%8,%9},{%0,%1,%2,%3};"
                 : "+f"(d[0]), "+f"(d[1]), "+f"(d[2]), "+f"(d[3])
                 : "r"(a0), "r"(a1), "r"(a2), "r"(a3), "r"(b0), "r"(b1));
}

__global__ void reset_kernel() { g_cnt = 0; g_cnt2 = 0; }

// ---------------- main router ----------------
__global__ void __launch_bounds__(256, 1)
router_kernel(const float* __restrict__ x, const float* __restrict__ W,
              float* __restrict__ out) {
    extern __shared__ float sm[];
    const int tid = threadIdx.x;
    const int wid = tid >> 5, lane = tid & 31;
    const int lq = lane & 3, lr = lane >> 2;

    const float* xg = x + (size_t)blockIdx.x * MTILE * KDIM;

    float4 rx[8], rw[2];
    auto ldg_chunk = [&](int c) {
        #pragma unroll
        for (int v = 0; v < 8; v++) {                 // x: 256 rows x 8 float4
            int fi = tid + 256 * v;
            int r = fi >> 3, j = fi & 7;
            rx[v] = *(const float4*)(xg + (size_t)r * KDIM + c * CK + j * 4);
        }
        #pragma unroll
        for (int v = 0; v < 2; v++) {                 // W: 64 rows x 8 float4
            int fi = tid + 256 * v;
            int e = fi >> 3, j = fi & 7;
            rw[v] = *(const float4*)(W + (size_t)e * KDIM + c * CK + j * 4);
        }
    };
    // k-interleaved layout: gmem col 4j+i -> smem pos (j>>1)*8 + 2i + (j&1)
    auto sts_chunk = [&](int c) {
        float* st = sm + (c & 1) * STAGEF;
        #pragma unroll
        for (int v = 0; v < 8; v++) {
            int fi = tid + 256 * v;
            int r = fi >> 3, j = fi & 7;
            float* p = st + r * RW + (j >> 1) * 8 + (j & 1);
            p[0] = rx[v].x; p[2] = rx[v].y; p[4] = rx[v].z; p[6] = rx[v].w;
        }
        #pragma unroll
        for (int v = 0; v < 2; v++) {
            int fi = tid + 256 * v;
            int e = fi >> 3, j = fi & 7;
            float* p = st + MTILE * RW + e * RW + (j >> 1) * 8 + (j & 1);
            p[0] = rw[v].x; p[2] = rw[v].y; p[4] = rw[v].z; p[6] = rw[v].w;
        }
    };

    float acc[2][8][4];
    #pragma unroll
    for (int mt = 0; mt < 2; mt++)
        #pragma unroll
        for (int j = 0; j < 8; j++)
            #pragma unroll
            for (int v = 0; v < 4; v++) acc[mt][j][v] = 0.0f;

    ldg_chunk(0); sts_chunk(0); ldg_chunk(1);
    __syncthreads();

    for (int c = 0; c < NCHUNK; c++) {
        const float* xb = sm + (c & 1) * STAGEF;
        const float* wb = xb + MTILE * RW;
        #pragma unroll
        for (int s = 0; s < 4; s++) {
            float2 b[8];
            #pragma unroll
            for (int j = 0; j < 8; j++)
                b[j] = *(const float2*)(wb + (j * 8 + lr) * RW + s * 8 + 2 * lq);
            float2 a0[2], a8[2];
            #pragma unroll
            for (int mt = 0; mt < 2; mt++) {
                const float* xr = xb + (wid * 32 + mt * 16 + lr) * RW + s * 8 + 2 * lq;
                a0[mt] = *(const float2*)(xr);
                a8[mt] = *(const float2*)(xr + 8 * RW);
            }
            #pragma unroll
            for (int j = 0; j < 8; j++)
                #pragma unroll
                for (int mt = 0; mt < 2; mt++)
                    mma8(acc[mt][j],
                         __float_as_uint(a0[mt].x), __float_as_uint(a8[mt].x),
                         __float_as_uint(a0[mt].y), __float_as_uint(a8[mt].y),
                         __float_as_uint(b[j].x),   __float_as_uint(b[j].y));
        }
        if (c + 1 < NCHUNK) sts_chunk(c + 1);
        __syncthreads();
        if (c + 2 < NCHUNK) ldg_chunk(c + 2);
    }

    // ---- score overlay: sc[256][65], mm[256], iz[256], red[4][64] ----
    float* sc = sm;
    float* mm = sc + 256 * 65;
    float* iz = mm + 256;
    float* red = iz + 256;

    #pragma unroll
    for (int mt = 0; mt < 2; mt++) {
        int r0 = wid * 32 + mt * 16 + lr;
        #pragma unroll
        for (int j = 0; j < 8; j++) {
            sc[r0 * 65 + j * 8 + 2 * lq]           = acc[mt][j][0];
            sc[r0 * 65 + j * 8 + 2 * lq + 1]       = acc[mt][j][1];
            sc[(r0 + 8) * 65 + j * 8 + 2 * lq]     = acc[mt][j][2];
            sc[(r0 + 8) * 65 + j * 8 + 2 * lq + 1] = acc[mt][j][3];
        }
    }
    __syncthreads();

    {   // one token per thread
        const int t = tid;
        const float* row = sc + t * 65;
        float m1 = -3e38f, m2 = -3e38f, m3 = -3e38f; int i1 = 0, i2 = 0;
        #pragma unroll 8
        for (int e = 0; e < 64; e++) {
            float v = row[e];
            if (v > m1)      { m3 = m2; m2 = m1; i2 = i1; m1 = v; i1 = e; }
            else if (v > m2) { m3 = m2; m2 = v; i2 = e; }
            else if (v > m3) { m3 = v; }
        }
        float Z = 0.0f;
        #pragma unroll 8
        for (int e = 0; e < 64; e++) Z += __expf(row[e] - m1);
        mm[t] = m1;
        iz[t] = 1.0f / Z;

        float e2 = __expf(m2 - m1);
        float w1 = 1.0f / (1.0f + e2);
        size_t T = (size_t)blockIdx.x * MTILE + t;
        out[2 * T]     = (float)i1;
        out[2 * T + 1] = (float)i2;
        out[2 * (size_t)NTOK + 2 * T]     = w1;
        out[2 * (size_t)NTOK + 2 * T + 1] = e2 * w1;
        if ((m1 - m2) < DELTA1 || (m2 - m3) < DELTA1) {
            int w = atomicAdd(&g_cnt, 1);
            g_list[w] = (int)T;
        }
    }
    __syncthreads();

    {   // deterministic per-CTA expert-usage partials
        const int e = tid & 63, seg = tid >> 6;
        float s = 0.0f;
        for (int t = seg * 64; t < seg * 64 + 64; t++)
            s += __expf(sc[t * 65 + e] - mm[t]) * iz[t];
        red[seg * 64 + e] = s;
    }
    __syncthreads();
    if (tid < NEXP)
        g_part[blockIdx.x * NEXP + tid] =
            red[tid] + red[64 + tid] + red[128 + tid] + red[192 + tid];
}

// ---- stage-1 fixup: exact fp32, W staged via smem, tracks top-4 ----
__global__ void __launch_bounds__(256)
fixup32_kernel(const float* __restrict__ x, const float* __restrict__ W,
               float* __restrict__ out) {
    __shared__ float wsm[64 * 36];
    __shared__ float xsm[4 * 36];
    __shared__ float scm[4 * 65];
    __shared__ int   toks[4];
    const int n = g_cnt;
    const int tid = threadIdx.x;
    const int slot = tid >> 6, e = tid & 63;

    for (int base = blockIdx.x * 4; base < n; base += gridDim.x * 4) {
        if (tid < 4) toks[tid] = (base + tid < n) ? g_list[base + tid] : g_list[base];
        __syncthreads();
        float acc = 0.0f;
        for (int kc = 0; kc < 64; kc++) {
            #pragma unroll
            for (int v = 0; v < 2; v++) {
                int fi = tid + 256 * v;
                int r = fi >> 3, c4 = fi & 7;
                *(float4*)&wsm[r * 36 + c4 * 4] =
                    *(const float4*)&W[(size_t)r * KDIM + kc * 32 + c4 * 4];
            }
            if (tid < 32) {
                int tk = tid >> 3, c4 = tid & 7;
                *(float4*)&xsm[tk * 36 + c4 * 4] =
                    *(const float4*)&x[(size_t)toks[tk] * KDIM + kc * 32 + c4 * 4];
            }
            __syncthreads();
            #pragma unroll
            for (int k4 = 0; k4 < 8; k4++) {
                float4 wv = *(const float4*)&wsm[e * 36 + k4 * 4];
                float4 xv = *(const float4*)&xsm[slot * 36 + k4 * 4];
                acc += wv.x * xv.x; acc += wv.y * xv.y;
                acc += wv.z * xv.z; acc += wv.w * xv.w;
            }
            __syncthreads();
        }
        scm[slot * 65 + e] = acc;
        __syncthreads();
        if (tid < 4 && base + tid < n) {
            const int tok = toks[tid];
            const float* row = scm + tid * 65;
            float m[4] = {-3e38f, -3e38f, -3e38f, -3e38f};
            int   id[4] = {0, 0, 0, 0};
            for (int q = 0; q < 64; q++) {
                float v = row[q];
                if (v > m[0])      { m[3]=m[2]; id[3]=id[2]; m[2]=m[1]; id[2]=id[1];
                                     m[1]=m[0]; id[1]=id[0]; m[0]=v; id[0]=q; }
                else if (v > m[1]) { m[3]=m[2]; id[3]=id[2]; m[2]=m[1]; id[2]=id[1];
                                     m[1]=v; id[1]=q; }
                else if (v > m[2]) { m[3]=m[2]; id[3]=id[2]; m[2]=v; id[2]=q; }
                else if (v > m[3]) { m[3]=v; id[3]=q; }
            }
            if ((m[0] - m[1]) < DELTA2 || (m[1] - m[2]) < DELTA2) {
                int q = atomicAdd(&g_cnt2, 1);
                g_list2[q] = tok;
                g_cand[q] = (unsigned)id[0] | ((unsigned)id[1] << 8) |
                            ((unsigned)id[2] << 16) | ((unsigned)id[3] << 24);
            } else {
                float e2 = expf(m[1] - m[0]);
                float w1 = 1.0f / (1.0f + e2);
                out[2 * (size_t)tok]     = (float)id[0];
                out[2 * (size_t)tok + 1] = (float)id[1];
                out[2 * (size_t)NTOK + 2 * (size_t)tok]     = w1;
                out[2 * (size_t)NTOK + 2 * (size_t)tok + 1] = e2 * w1;
            }
        }
        __syncthreads();
    }
}

// ---- stage-2 fixup (blocks 0..255): fp64 on 4 candidate experts / token
// ---- aux loss      (block 256)
__global__ void __launch_bounds__(128)
fixup64_aux_kernel(const float* __restrict__ x, const float* __restrict__ W,
                   float* __restrict__ out) {
    if (blockIdx.x == 256) {   // ---- aux path ----
        __shared__ float ps[2][64];
        const int tid = threadIdx.x;
        const int e = tid & 63, half = tid >> 6;
        float s = 0.0f;
        for (int c = half * 64; c < half * 64 + 64; c++)
            s += g_part[c * NEXP + e];
        ps[half][e] = s;
        __syncthreads();
        if (tid < 64) {
            float u = (ps[0][tid] + ps[1][tid]) * (1.0f / (float)NTOK);
            ps[0][tid] = u * u;
        }
        __syncthreads();
        if (tid < 32) {
            float v = ps[0][tid] + ps[0][tid + 32];
            #pragma unroll
            for (int o = 16; o > 0; o >>= 1) v += __shfl_xor_sync(0xffffffffu, v, o);
            if (tid == 0) out[131072] = 64.0f * v;
        }
        return;
    }
    // ---- fp64 candidate recompute: warp wi -> candidate wi ----
    __shared__ double sv[4];
    __shared__ int    se[4];
    const int n = g_cnt2;
    const int wi = threadIdx.x >> 5, l = threadIdx.x & 31;
    for (int q = blockIdx.x; q < n; q += 256) {
        const int tok = g_list2[q];
        const int e = (int)((g_cand[q] >> (8 * wi)) & 255u);
        const float* xr = x + (size_t)tok * KDIM;
        const float* wr = W + (size_t)e * KDIM;
        double c0 = 0.0, c1 = 0.0, c2 = 0.0, c3 = 0.0;
        #pragma unroll 4
        for (int j = 0; j < 64; j += 4) {
            c0 += (double)xr[(j + 0) * 32 + l] * (double)wr[(j + 0) * 32 + l];
            c1 += (double)xr[(j + 1) * 32 + l] * (double)wr[(j + 1) * 32 + l];
            c2 += (double)xr[(j + 2) * 32 + l] * (double)wr[(j + 2) * 32 + l];
            c3 += (double)xr[(j + 3) * 32 + l] * (double)wr[(j + 3) * 32 + l];
        }
        double s = (c0 + c1) + (c2 + c3);
        #pragma unroll
        for (int o = 16; o > 0; o >>= 1) s += __shfl_xor_sync(0xffffffffu, s, o);
        if (l == 0) { sv[wi] = s; se[wi] = e; }
        __syncthreads();
        if (threadIdx.x == 0) {
            // top-2 among 4 candidates; ties -> lower expert index (jax order)
            int b1 = 0;
            for (int k = 1; k < 4; k++)
                if (sv[k] > sv[b1] || (sv[k] == sv[b1] && se[k] < se[b1])) b1 = k;
            int b2 = (b1 == 0) ? 1 : 0;
            for (int k = 0; k < 4; k++) {
                if (k == b1) continue;
                if (sv[k] > sv[b2] || (sv[k] == sv[b2] && se[k] < se[b2])) b2 = k;
            }
            double e2 = exp(sv[b2] - sv[b1]);
            double w1 = 1.0 / (1.0 + e2);
            out[2 * (size_t)tok]     = (float)se[b1];
            out[2 * (size_t)tok + 1] = (float)se[b2];
            out[2 * (size_t)NTOK + 2 * (size_t)tok]     = (float)w1;
            out[2 * (size_t)NTOK + 2 * (size_t)tok + 1] = (float)(e2 * w1);
        }
        __syncthreads();
    }
}

extern "C" void kernel_launch(void* const* d_in, const int* in_sizes, int n_in,
                              void* d_out, int out_size) {
    const float* x = (const float*)d_in[0];
    const float* W = (const float*)d_in[1];
    float* out = (float*)d_out;
    cudaFuncSetAttribute(router_kernel, cudaFuncAttributeMaxDynamicSharedMemorySize, SMEM_REQ);
    reset_kernel<<<1, 1>>>();
    router_kernel<<<NCTA, 256, SMEM_REQ>>>(x, W, out);
    fixup32_kernel<<<128, 256>>>(x, W, out);
    fixup64_aux_kernel<<<257, 128>>>(x, W, out);
}

// round 8
// speedup vs baseline: 1.6471x; 1.0545x over previous
#include <cuda_runtime.h>
#include <cstdint>

// Router_63900523430579 (GB300/sm_103): scores = x[32768,2048] @ W[64,2048]^T
// via mma.sync.m16n8k8 tf32, cp.async 4-stage pipeline.
// out f32: [0,65536) top2 idx ; [65536,131072) top2 weights ; [131072] aux loss

#define KDIM   2048
#define NTOK   32768
#define NEXP   64
#define MTILE  256
#define NCTA   (NTOK / MTILE)          // 128
#define CK     32                      // K floats per chunk
#define NCHUNK (KDIM / CK)             // 64
#define RW     40                      // smem row stride (floats)
#define STAGEF ((MTILE + NEXP) * RW)   // 12800 floats / stage
#define SMEM_REQ (4 * STAGEF * 4)      // 204800 B
#define DELTA1 3.0e-3f

__device__ float    g_Wp[NEXP * KDIM];      // k-interleaved W
__device__ float    g_part[NCTA * NEXP];
__device__ int      g_cnt1, g_cnt2;
__device__ int      g_list1[NTOK], g_list2[NTOK];
__device__ unsigned g_cand[NTOK];

__device__ __forceinline__ void mma8(float* d, uint32_t a0, uint32_t a1,
                                     uint32_t a2, uint32_t a3,
                                     uint32_t b0, uint32_t b1) {
    asm volatile("mma.sync.aligned.m16n8k8.row.col.f32.tf32.tf32.f32 "
                 "{%0,%1,%2,%3},{%4,%5,%6,%7},{%8,%9},{%0,%1,%2,%3};"
                 : "+f"(d[0]), "+f"(d[1]), "+f"(d[2]), "+f"(d[3])
                 : "r"(a0), "r"(a1), "r"(a2), "r"(a3), "r"(b0), "r"(b1));
}
__device__ __forceinline__ void cp16(uint32_t s, const void* g) {
    asm volatile("cp.async.cg.shared.global [%0], [%1], 16;\n" :: "r"(s), "l"(g));
}
#define CP_COMMIT() asm volatile("cp.async.commit_group;\n")
#define CP_WAIT(n)  asm volatile("cp.async.wait_group %0;\n" :: "n"(n))

// ---- prep: reset counters + permute W (k-interleave within 32-blocks) ----
// block of 32: elem k=4j+i  ->  pos (j>>1)*8 + 2i + (j&1)   (pairs (k,k+4) adjacent)
__global__ void prep_kernel(const float* __restrict__ W) {
    int fi = blockIdx.x * blockDim.x + threadIdx.x;    // over 64*512 float4
    if (fi < NEXP * (KDIM / 4)) {
        int e = fi >> 9, j_abs = fi & 511;
        int c = j_abs >> 3, j = j_abs & 7;
        float4 w = *(const float4*)(W + (size_t)e * KDIM + c * 32 + j * 4);
        float* dst = g_Wp + (size_t)e * KDIM + c * 32 + (j >> 1) * 8 + (j & 1);
        dst[0] = w.x; dst[2] = w.y; dst[4] = w.z; dst[6] = w.w;
    }
    if (fi == 0) { g_cnt1 = 0; g_cnt2 = 0; }
}

// ---------------- main router ----------------
__global__ void __launch_bounds__(256, 1)
router_kernel(const float* __restrict__ x, float* __restrict__ out) {
    extern __shared__ float sm[];
    const uint32_t smb = (uint32_t)__cvta_generic_to_shared(sm);
    const int tid = threadIdx.x;
    const int wid = tid >> 5, lane = tid & 31;
    const int lq = lane & 3, lr = lane >> 2;

    const float* xg = x + (size_t)blockIdx.x * MTILE * KDIM;

    // per-thread: 8 x-cp16 (256 rows x 8 f4 / 256 thr) + 2 W-cp16
    const int xr_ = tid >> 3, xj = tid & 7;            // rows xr_, xr_+... (8 per thread? no: fi=tid+256v)
    auto issue_chunk = [&](int c) {
        uint32_t st = smb + ((c & 3) * STAGEF) * 4;
        #pragma unroll
        for (int v = 0; v < 8; v++) {
            int fi = tid + 256 * v;
            int r = fi >> 3, j = fi & 7;
            cp16(st + (uint32_t)(r * RW + j * 4) * 4,
                 xg + (size_t)r * KDIM + c * CK + j * 4);
        }
        #pragma unroll
        for (int v = 0; v < 2; v++) {
            int fi = tid + 256 * v;
            int e = fi >> 3, j = fi & 7;
            cp16(st + (uint32_t)(MTILE * RW + e * RW + j * 4) * 4,
                 g_Wp + (size_t)e * KDIM + c * CK + j * 4);
        }
        CP_COMMIT();
    };

    float acc[2][8][4];
    #pragma unroll
    for (int mt = 0; mt < 2; mt++)
        #pragma unroll
        for (int j = 0; j < 8; j++)
            #pragma unroll
            for (int v = 0; v < 4; v++) acc[mt][j][v] = 0.0f;

    issue_chunk(0); issue_chunk(1); issue_chunk(2);

    for (int c = 0; c < NCHUNK; c++) {
        if (c < 62)      CP_WAIT(2);
        else if (c == 62) CP_WAIT(1);
        else              CP_WAIT(0);
        __syncthreads();
        if (c + 3 < NCHUNK) issue_chunk(c + 3);

        const float* xb = sm + (c & 3) * STAGEF;
        const float* wb = xb + MTILE * RW;
        #pragma unroll
        for (int s = 0; s < 4; s++) {
            float2 b[8];
            #pragma unroll
            for (int j = 0; j < 8; j++)
                b[j] = *(const float2*)(wb + (j * 8 + lr) * RW + s * 8 + 2 * lq);
            #pragma unroll
            for (int mt = 0; mt < 2; mt++) {
                const float* xr = xb + (wid * 32 + mt * 16 + lr) * RW + s * 8 + lq;
                uint32_t a0 = __float_as_uint(xr[0]);
                uint32_t a1 = __float_as_uint(xr[8 * RW]);
                uint32_t a2 = __float_as_uint(xr[4]);
                uint32_t a3 = __float_as_uint(xr[8 * RW + 4]);
                #pragma unroll
                for (int j = 0; j < 8; j++)
                    mma8(acc[mt][j], a0, a1, a2, a3,
                         __float_as_uint(b[j].x), __float_as_uint(b[j].y));
            }
        }
        __syncthreads();
    }

    // ---- score overlay: sc[256][65], mm[256], iz[256], red[4][64] ----
    float* sc = sm;
    float* mm = sc + 256 * 65;
    float* iz = mm + 256;
    float* red = iz + 256;

    #pragma unroll
    for (int mt = 0; mt < 2; mt++) {
        int r0 = wid * 32 + mt * 16 + lr;
        #pragma unroll
        for (int j = 0; j < 8; j++) {
            sc[r0 * 65 + j * 8 + 2 * lq]           = acc[mt][j][0];
            sc[r0 * 65 + j * 8 + 2 * lq + 1]       = acc[mt][j][1];
            sc[(r0 + 8) * 65 + j * 8 + 2 * lq]     = acc[mt][j][2];
            sc[(r0 + 8) * 65 + j * 8 + 2 * lq + 1] = acc[mt][j][3];
        }
    }
    __syncthreads();

    {   // one token per thread: top-4 + softmax + ambiguity routing
        const int t = tid;
        const float* row = sc + t * 65;
        float m[4] = {-3e38f, -3e38f, -3e38f, -3e38f};
        int   id[4] = {0, 0, 0, 0};
        #pragma unroll 8
        for (int e = 0; e < 64; e++) {
            float v = row[e];
            if (v > m[0])      { m[3]=m[2]; id[3]=id[2]; m[2]=m[1]; id[2]=id[1];
                                 m[1]=m[0]; id[1]=id[0]; m[0]=v; id[0]=e; }
            else if (v > m[1]) { m[3]=m[2]; id[3]=id[2]; m[2]=m[1]; id[2]=id[1];
                                 m[1]=v; id[1]=e; }
            else if (v > m[2]) { m[3]=m[2]; id[3]=id[2]; m[2]=v; id[2]=e; }
            else if (v > m[3]) { m[3]=v; id[3]=e; }
        }
        float Z = 0.0f;
        #pragma unroll 8
        for (int e = 0; e < 64; e++) Z += __expf(row[e] - m[0]);
        mm[t] = m[0];
        iz[t] = 1.0f / Z;

        float e2 = __expf(m[1] - m[0]);
        float w1 = 1.0f / (1.0f + e2);
        size_t T = (size_t)blockIdx.x * MTILE + t;
        out[2 * T]     = (float)id[0];
        out[2 * T + 1] = (float)id[1];
        out[2 * (size_t)NTOK + 2 * T]     = w1;
        out[2 * (size_t)NTOK + 2 * T + 1] = e2 * w1;

        if ((m[0] - m[1]) < DELTA1 || (m[1] - m[2]) < DELTA1) {
            if ((m[1] - m[3]) < DELTA1) {          // 4th also close: full recompute
                int q = atomicAdd(&g_cnt2, 1);
                g_list2[q] = (int)T;
            } else {                               // top-2 provably within top-4
                int q = atomicAdd(&g_cnt1, 1);
                g_list1[q] = (int)T;
                g_cand[q] = (unsigned)id[0] | ((unsigned)id[1] << 8) |
                            ((unsigned)id[2] << 16) | ((unsigned)id[3] << 24);
            }
        }
    }
    __syncthreads();

    {   // deterministic per-CTA expert-usage partials
        const int e = tid & 63, seg = tid >> 6;
        float s = 0.0f;
        for (int t = seg * 64; t < seg * 64 + 64; t++)
            s += __expf(sc[t * 65 + e] - mm[t]) * iz[t];
        red[seg * 64 + e] = s;
    }
    __syncthreads();
    if (tid < NEXP)
        g_part[blockIdx.x * NEXP + tid] =
            red[tid] + red[64 + tid] + red[128 + tid] + red[192 + tid];
}

// ---- fixup (blocks 0..255): fp64 candidates, then fp64 full; block 256: aux
__global__ void __launch_bounds__(128)
fixup_aux_kernel(const float* __restrict__ x, const float* __restrict__ W,
                 float* __restrict__ out) {
    if (blockIdx.x == 256) {   // ---- aux path ----
        __shared__ float ps[2][64];
        const int tid = threadIdx.x;
        const int e = tid & 63, half = tid >> 6;
        float s = 0.0f;
        for (int c = half * 64; c < half * 64 + 64; c++)
            s += g_part[c * NEXP + e];
        ps[half][e] = s;
        __syncthreads();
        if (tid < 64) {
            float u = (ps[0][tid] + ps[1][tid]) * (1.0f / (float)NTOK);
            ps[0][tid] = u * u;
        }
        __syncthreads();
        if (tid < 32) {
            float v = ps[0][tid] + ps[0][tid + 32];
            #pragma unroll
            for (int o = 16; o > 0; o >>= 1) v += __shfl_xor_sync(0xffffffffu, v, o);
            if (tid == 0) out[131072] = 64.0f * v;
        }
        return;
    }
    const int wi = threadIdx.x >> 5, l = threadIdx.x & 31;

    // ---- candidate tokens: warp wi -> candidate wi ----
    {
        __shared__ double sv[4];
        __shared__ int    se[4];
        const int n = g_cnt1;
        for (int q = blockIdx.x; q < n; q += 256) {
            const int tok = g_list1[q];
            const int e = (int)((g_cand[q] >> (8 * wi)) & 255u);
            const float* xr = x + (size_t)tok * KDIM;
            const float* wr = W + (size_t)e * KDIM;
            double c0 = 0.0, c1 = 0.0, c2 = 0.0, c3 = 0.0;
            #pragma unroll 4
            for (int j = 0; j < 64; j += 4) {
                c0 += (double)xr[(j + 0) * 32 + l] * (double)wr[(j + 0) * 32 + l];
                c1 += (double)xr[(j + 1) * 32 + l] * (double)wr[(j + 1) * 32 + l];
                c2 += (double)xr[(j + 2) * 32 + l] * (double)wr[(j + 2) * 32 + l];
                c3 += (double)xr[(j + 3) * 32 + l] * (double)wr[(j + 3) * 32 + l];
            }
            double s = (c0 + c1) + (c2 + c3);
            #pragma unroll
            for (int o = 16; o > 0; o >>= 1) s += __shfl_xor_sync(0xffffffffu, s, o);
            if (l == 0) { sv[wi] = s; se[wi] = e; }
            __syncthreads();
            if (threadIdx.x == 0) {
                int b1 = 0;
                for (int k = 1; k < 4; k++)
                    if (sv[k] > sv[b1] || (sv[k] == sv[b1] && se[k] < se[b1])) b1 = k;
                int b2 = (b1 == 0) ? 1 : 0;
                for (int k = 0; k < 4; k++) {
                    if (k == b1) continue;
                    if (sv[k] > sv[b2] || (sv[k] == sv[b2] && se[k] < se[b2])) b2 = k;
                }
                double e2 = exp(sv[b2] - sv[b1]);
                double w1 = 1.0 / (1.0 + e2);
                out[2 * (size_t)tok]     = (float)se[b1];
                out[2 * (size_t)tok + 1] = (float)se[b2];
                out[2 * (size_t)NTOK + 2 * (size_t)tok]     = (float)w1;
                out[2 * (size_t)NTOK + 2 * (size_t)tok + 1] = (float)(e2 * w1);
            }
            __syncthreads();
        }
    }

    // ---- full-64 tokens (rare): warp wi covers experts wi*16..wi*16+15 ----
    {
        __shared__ double sh[64];
        const int n = g_cnt2;
        for (int q = blockIdx.x; q < n; q += 256) {
            const int tok = g_list2[q];
            const float* xr = x + (size_t)tok * KDIM;
            for (int e16 = 0; e16 < 16; e16++) {
                int e = wi * 16 + e16;
                const float* wr = W + (size_t)e * KDIM;
                double c0 = 0.0, c1 = 0.0, c2 = 0.0, c3 = 0.0;
                #pragma unroll 4
                for (int j = 0; j < 64; j += 4) {
                    c0 += (double)xr[(j + 0) * 32 + l] * (double)wr[(j + 0) * 32 + l];
                    c1 += (double)xr[(j + 1) * 32 + l] * (double)wr[(j + 1) * 32 + l];
                    c2 += (double)xr[(j + 2) * 32 + l] * (double)wr[(j + 2) * 32 + l];
                    c3 += (double)xr[(j + 3) * 32 + l] * (double)wr[(j + 3) * 32 + l];
                }
                double s = (c0 + c1) + (c2 + c3);
                #pragma unroll
                for (int o = 16; o > 0; o >>= 1) s += __shfl_xor_sync(0xffffffffu, s, o);
                if (l == 0) sh[e] = s;
            }
            __syncthreads();
            if (threadIdx.x == 0) {
                double m1 = -1e300, m2 = -1e300; int i1 = 0, i2 = 0;
                for (int e = 0; e < 64; e++)
                    if (sh[e] > m1) { m1 = sh[e]; i1 = e; }
                for (int e = 0; e < 64; e++) {
                    if (e == i1) continue;
                    if (sh[e] > m2) { m2 = sh[e]; i2 = e; }
                }
                double e2 = exp(m2 - m1);
                double w1 = 1.0 / (1.0 + e2);
                out[2 * (size_t)tok]     = (float)i1;
                out[2 * (size_t)tok + 1] = (float)i2;
                out[2 * (size_t)NTOK + 2 * (size_t)tok]     = (float)w1;
                out[2 * (size_t)NTOK + 2 * (size_t)tok + 1] = (float)(e2 * w1);
            }
            __syncthreads();
        }
    }
}

extern "C" void kernel_launch(void* const* d_in, const int* in_sizes, int n_in,
                              void* d_out, int out_size) {
    const float* x = (const float*)d_in[0];
    const float* W = (const float*)d_in[1];
    float* out = (float*)d_out;
    cudaFuncSetAttribute(router_kernel, cudaFuncAttributeMaxDynamicSharedMemorySize, SMEM_REQ);
    prep_kernel<<<128, 256>>>(W);
    router_kernel<<<NCTA, 256, SMEM_REQ>>>(x, out);
    fixup_aux_kernel<<<257, 128>>>(x, W, out);
}